// round 10
// baseline (speedup 1.0000x reference)
#include <cuda_runtime.h>
#include <cuda_bf16.h>
#include <cuda_fp16.h>
#include <cuda_fp8.h>
#include <cstdint>
#include <math.h>

// NT-Xent loss, symmetric-triangle fp8 mma.sync, packed f16x2 epilogue.

#define NROWS 8192
#define HALF_N 4096
#define DIM 256
#define TILE 128
#define GEMM_CTAS 296       // 148 SMs x occ 2, single wave
#define ROWB 256            // bytes per tile row (256 fp8)
#define NSLOT 128
#define SCALE_EX2 2.8853900817779268f   // 2/ln2
#define SC_H2 0x41C541C5u               // (half)2.8848 packed x2

__device__ __align__(16) uint8_t g_zq[NROWS * DIM];
__device__ float g_partial[(size_t)NROWS * NSLOT];
__device__ float g_slabel[NROWS];
__device__ float g_bsum[256];
__device__ unsigned g_ticket = 0;

__device__ __forceinline__ uint32_t smem_u32(const void* p) {
    uint32_t a;
    asm("{ .reg .u64 t; cvta.to.shared.u64 t, %1; cvt.u32.u64 %0, t; }" : "=r"(a) : "l"(p));
    return a;
}
__device__ __forceinline__ float ex2f(float x) {
    float r;
    asm("ex2.approx.f32 %0, %1;" : "=f"(r) : "f"(x));
    return r;
}
__device__ __forceinline__ uint32_t cvt_h2(float hi, float lo) {
    uint32_t r;
    asm("cvt.rn.f16x2.f32 %0, %1, %2;" : "=r"(r) : "f"(hi), "f"(lo));
    return r;
}
__device__ __forceinline__ uint32_t hmul2(uint32_t a, uint32_t b) {
    uint32_t r;
    asm("mul.rn.f16x2 %0, %1, %2;" : "=r"(r) : "r"(a), "r"(b));
    return r;
}
__device__ __forceinline__ uint32_t hadd2(uint32_t a, uint32_t b) {
    uint32_t r;
    asm("add.rn.f16x2 %0, %1, %2;" : "=r"(r) : "r"(a), "r"(b));
    return r;
}
__device__ __forceinline__ uint32_t h2ex2(uint32_t a) {
    uint32_t r;
    asm("ex2.approx.f16x2 %0, %1;" : "=r"(r) : "r"(a));
    return r;
}
__device__ __forceinline__ float2 h2_to_f2(uint32_t a) {
    __half2 h = *(__half2*)&a;
    return __half22float2(h);   // .x = lo, .y = hi
}

#define CP16(dst, src) asm volatile("cp.async.cg.shared.global [%0], [%1], 16;" :: "r"(dst), "l"(src) : "memory")
#define CP_COMMIT()    asm volatile("cp.async.commit_group;" ::: "memory")
#define CP_WAIT1()     asm volatile("cp.async.wait_group 1;" ::: "memory")
#define CP_WAIT0()     asm volatile("cp.async.wait_group 0;" ::: "memory")

__device__ __forceinline__ void ldm_x4(uint32_t* r, uint32_t addr) {
    asm volatile("ldmatrix.sync.aligned.m8n8.x4.shared.b16 {%0,%1,%2,%3}, [%4];"
                 : "=r"(r[0]), "=r"(r[1]), "=r"(r[2]), "=r"(r[3]) : "r"(addr));
}
__device__ __forceinline__ void mma_fp8(float* c, const uint32_t* a, uint32_t b0, uint32_t b1) {
    asm volatile("mma.sync.aligned.m16n8k32.row.col.f32.e4m3.e4m3.f32 "
                 "{%0,%1,%2,%3}, {%4,%5,%6,%7}, {%8,%9}, {%0,%1,%2,%3};"
                 : "+f"(c[0]), "+f"(c[1]), "+f"(c[2]), "+f"(c[3])
                 : "r"(a[0]), "r"(a[1]), "r"(a[2]), "r"(a[3]), "r"(b0), "r"(b1));
}

__device__ __forceinline__ void tile_ij(int t, int& i, int& j) {
    int p = t / 65;
    int q = t - p * 65;
    if (q < 64 - p) { i = p; j = p + q; }
    else            { i = 63 - p; j = q - 1; }
}

__device__ __forceinline__ void load_tile(uint32_t dst, int tile, int tid) {
    const char* base = (const char*)g_zq + (size_t)tile * TILE * ROWB;
    #pragma unroll
    for (int i = 0; i < 8; i++) {
        int idx = tid + 256 * i;
        int r = idx >> 4;
        int c = idx & 15;
        uint32_t d = dst + r * ROWB + ((c ^ (r & 7)) << 4);
        CP16(d, base + (size_t)r * ROWB + c * 16);
    }
}

// ---------------- Kernel 1: normalize fp32 -> e4m3, warp per row ----------------
__global__ void normalize_kernel(const float* __restrict__ zi,
                                 const float* __restrict__ zj) {
    const int wid = threadIdx.x >> 5, lane = threadIdx.x & 31;
    const int row = blockIdx.x * 8 + wid;
    const float* src = (row < HALF_N) ? (zi + (size_t)row * DIM)
                                      : (zj + (size_t)(row - HALF_N) * DIM);
    const float4* s4 = (const float4*)src;
    float4 a = s4[lane * 2];
    float4 b = s4[lane * 2 + 1];
    float ss = a.x*a.x + a.y*a.y + a.z*a.z + a.w*a.w
             + b.x*b.x + b.y*b.y + b.z*b.z + b.w*b.w;
    #pragma unroll
    for (int o = 16; o > 0; o >>= 1) ss += __shfl_xor_sync(0xffffffffu, ss, o);
    float inv = rsqrtf(fmaxf(ss, 1e-16f));
    unsigned short q0 = __nv_cvt_float2_to_fp8x2(make_float2(a.x*inv, a.y*inv), __NV_SATFINITE, __NV_E4M3);
    unsigned short q1 = __nv_cvt_float2_to_fp8x2(make_float2(a.z*inv, a.w*inv), __NV_SATFINITE, __NV_E4M3);
    unsigned short q2 = __nv_cvt_float2_to_fp8x2(make_float2(b.x*inv, b.y*inv), __NV_SATFINITE, __NV_E4M3);
    unsigned short q3 = __nv_cvt_float2_to_fp8x2(make_float2(b.z*inv, b.w*inv), __NV_SATFINITE, __NV_E4M3);
    uint2 out;
    out.x = (uint32_t)q0 | ((uint32_t)q1 << 16);
    out.y = (uint32_t)q2 | ((uint32_t)q3 << 16);
    *(uint2*)(g_zq + (size_t)row * ROWB + lane * 8) = out;
}

// ---------------- Kernel 2: triangle sim GEMM + packed dual exp-sum -------------
__global__ __launch_bounds__(256, 2) void simloss_kernel() {
    extern __shared__ char smem[];
    __shared__ float colstage[4][128];
    const uint32_t sb = smem_u32(smem);
    const uint32_t A_OFF = sb;
    const uint32_t B_OFF[2] = { sb + 32768, sb + 65536 };

    const int tid = threadIdx.x, wid = tid >> 5, lane = tid & 31;
    const int wm = wid & 3, wn = wid >> 2;
    const int b = blockIdx.x;
    const int t0 = b * 7 + min(b, 8);
    const int cnt = 7 + (b < 8 ? 1 : 0);

    int i0, j0, i1x, j1x;
    tile_ij(t0, i0, j0);
    tile_ij(t0 + 1, i1x, j1x);
    load_tile(A_OFF, i0, tid);
    load_tile(B_OFF[0], j0, tid);
    CP_COMMIT();
    load_tile(B_OFF[1], j1x, tid);
    CP_COMMIT();

    const int h = lane >> 4;
    uint32_t a_row[2], a_x[2];
    #pragma unroll
    for (int m = 0; m < 2; m++) {
        int r = wm * 32 + m * 16 + (lane & 15);
        a_row[m] = A_OFF + r * ROWB;
        a_x[m] = r & 7;
    }
    uint32_t b_row[4], b_x[4];
    #pragma unroll
    for (int n = 0; n < 4; n++) {
        int r = wn * 64 + n * 16 + (lane & 15);
        b_row[n] = r * ROWB;
        b_x[n] = r & 7;
    }

    const int lr = lane >> 2;
    const int c4 = lane & 3;

    int iprev = i0;
    for (int k = 0; k < cnt; k++) {
        int ii, jj;
        tile_ij(t0 + k, ii, jj);
        const bool achg = (k > 0) && (ii != iprev);
        iprev = ii;

        if (achg) CP_WAIT0(); else CP_WAIT1();
        __syncthreads();

        // ---- MMA 128x128x256 e4m3 ----
        const uint32_t bb = B_OFF[k & 1];
        float acc[2][8][4];
        #pragma unroll
        for (int m = 0; m < 2; m++)
            #pragma unroll
            for (int n = 0; n < 8; n++)
                #pragma unroll
                for (int q = 0; q < 4; q++) acc[m][n][q] = 0.f;

        #pragma unroll
        for (int ks = 0; ks < 8; ks++) {
            const uint32_t c = 2 * ks + h;
            uint32_t ar[2][4], br[4][4];
            #pragma unroll
            for (int m = 0; m < 2; m++)
                ldm_x4(ar[m], a_row[m] + ((c ^ a_x[m]) << 4));
            #pragma unroll
            for (int n = 0; n < 4; n++)
                ldm_x4(br[n], bb + b_row[n] + ((c ^ b_x[n]) << 4));
            #pragma unroll
            for (int m = 0; m < 2; m++)
                #pragma unroll
                for (int n = 0; n < 4; n++) {
                    mma_fp8(acc[m][2 * n],     ar[m], br[n][0], br[n][2]);
                    mma_fp8(acc[m][2 * n + 1], ar[m], br[n][1], br[n][3]);
                }
        }

        __syncthreads();

        if (k + 1 < cnt) {
            int in, jn;
            tile_ij(t0 + k + 1, in, jn);
            if (in != ii) load_tile(A_OFF, in, tid);
        }
        if (k + 2 < cnt) {
            int in2, jn2;
            tile_ij(t0 + k + 2, in2, jn2);
            load_tile(B_OFF[k & 1], jn2, tid);
        }
        CP_COMMIT();

        const bool isdiag = (ii == jj);
        const bool islab = ((ii ^ jj) == 32);

        if (!isdiag && !islab) {
            // ---------- FAST PATH: packed f16x2 ----------
            // rs2[m]: lo = rh0 partial, hi = rh1 partial
            // cs2[n][kp]: both halves are partials of cs[n][kp]
            uint32_t rs2[2] = {0u, 0u};
            uint32_t cs2[8][2];
            #pragma unroll
            for (int n = 0; n < 8; n++) { cs2[n][0] = 0u; cs2[n][1] = 0u; }

            #pragma unroll
            for (int m = 0; m < 2; m++)
                #pragma unroll
                for (int n = 0; n < 8; n++) {
                    // pair A = (hi=q2[rh1,kp0], lo=q0[rh0,kp0])
                    uint32_t pa = cvt_h2(acc[m][n][2], acc[m][n][0]);
                    // pair B = (hi=q3[rh1,kp1], lo=q1[rh0,kp1])
                    uint32_t pb = cvt_h2(acc[m][n][3], acc[m][n][1]);
                    pa = h2ex2(hmul2(pa, SC_H2));
                    pb = h2ex2(hmul2(pb, SC_H2));
                    rs2[m] = hadd2(rs2[m], pa);
                    rs2[m] = hadd2(rs2[m], pb);
                    cs2[n][0] = hadd2(cs2[n][0], pa);
                    cs2[n][1] = hadd2(cs2[n][1], pb);
                }

            // Row reduce over lane bits 0-1 (packed).
            #pragma unroll
            for (int m = 0; m < 2; m++) {
                rs2[m] = hadd2(rs2[m], __shfl_xor_sync(0xffffffffu, rs2[m], 1));
                rs2[m] = hadd2(rs2[m], __shfl_xor_sync(0xffffffffu, rs2[m], 2));
            }
            if (c4 == 0) {
                #pragma unroll
                for (int m = 0; m < 2; m++) {
                    float2 f = h2_to_f2(rs2[m]);   // .x = rh0, .y = rh1
                    int g0 = TILE * ii + wm * 32 + m * 16 + lr;
                    g_partial[(size_t)g0 * NSLOT + 2 * jj + wn] = f.x;
                    g_partial[(size_t)(g0 + 8) * NSLOT + 2 * jj + wn] = f.y;
                }
            }

            // Column reduce over lane bits 2-4 (packed), then wm via smem.
            #pragma unroll
            for (int n = 0; n < 8; n++)
                #pragma unroll
                for (int kp = 0; kp < 2; kp++) {
                    cs2[n][kp] = hadd2(cs2[n][kp], __shfl_xor_sync(0xffffffffu, cs2[n][kp], 4));
                    cs2[n][kp] = hadd2(cs2[n][kp], __shfl_xor_sync(0xffffffffu, cs2[n][kp], 8));
                    cs2[n][kp] = hadd2(cs2[n][kp], __shfl_xor_sync(0xffffffffu, cs2[n][kp], 16));
                }
            if (lane < 4) {
                #pragma unroll
                for (int n = 0; n < 8; n++)
                    #pragma unroll
                    for (int kp = 0; kp < 2; kp++) {
                        float2 f = h2_to_f2(cs2[n][kp]);
                        colstage[wm][wn * 64 + n * 8 + lane * 2 + kp] = f.x + f.y;
                    }
            }
            __syncthreads();
            if (tid < 128) {
                float v = colstage[0][tid] + colstage[1][tid]
                        + colstage[2][tid] + colstage[3][tid];
                size_t base = (size_t)(TILE * jj + tid) * NSLOT;
                g_partial[base + 2 * ii] = v;
                g_partial[base + 2 * ii + 1] = 0.f;
            }
        } else {
            // ---------- SPECIAL PATH (diag / label tiles): exact f32 ----------
            float rs[2][2] = {{0.f, 0.f}, {0.f, 0.f}};
            float cs[8][2];
            #pragma unroll
            for (int n = 0; n < 8; n++) { cs[n][0] = 0.f; cs[n][1] = 0.f; }

            #pragma unroll
            for (int m = 0; m < 2; m++)
                #pragma unroll
                for (int n = 0; n < 8; n++)
                    #pragma unroll
                    for (int q = 0; q < 4; q++) {
                        const int rh = q >> 1, kp = q & 1;
                        const int rloc = wm * 32 + m * 16 + lr + rh * 8;
                        const int cloc = wn * 64 + n * 8 + c4 * 2 + kp;
                        float e = ex2f(acc[m][n][q] * SCALE_EX2);
                        bool dg = isdiag && (rloc == cloc);
                        if (!dg) { rs[m][rh] += e; cs[n][kp] += e; }
                        if (islab && rloc == cloc) {
                            float s = 2.0f * acc[m][n][q];
                            g_slabel[TILE * ii + rloc] = s;
                            g_slabel[TILE * jj + cloc] = s;
                        }
                    }

            #pragma unroll
            for (int m = 0; m < 2; m++)
                #pragma unroll
                for (int rh = 0; rh < 2; rh++) {
                    rs[m][rh] += __shfl_xor_sync(0xffffffffu, rs[m][rh], 1);
                    rs[m][rh] += __shfl_xor_sync(0xffffffffu, rs[m][rh], 2);
                }
            if (c4 == 0) {
                #pragma unroll
                for (int m = 0; m < 2; m++)
                    #pragma unroll
                    for (int rh = 0; rh < 2; rh++) {
                        int grow = TILE * ii + wm * 32 + m * 16 + lr + rh * 8;
                        g_partial[(size_t)grow * NSLOT + 2 * jj + wn] = rs[m][rh];
                    }
            }

            #pragma unroll
            for (int n = 0; n < 8; n++)
                #pragma unroll
                for (int kp = 0; kp < 2; kp++) {
                    cs[n][kp] += __shfl_xor_sync(0xffffffffu, cs[n][kp], 4);
                    cs[n][kp] += __shfl_xor_sync(0xffffffffu, cs[n][kp], 8);
                    cs[n][kp] += __shfl_xor_sync(0xffffffffu, cs[n][kp], 16);
                }
            if (lane < 4) {
                #pragma unroll
                for (int n = 0; n < 8; n++)
                    #pragma unroll
                    for (int kp = 0; kp < 2; kp++)
                        colstage[wm][wn * 64 + n * 8 + lane * 2 + kp] = cs[n][kp];
            }
            __syncthreads();
            if (!isdiag && tid < 128) {
                float v = colstage[0][tid] + colstage[1][tid]
                        + colstage[2][tid] + colstage[3][tid];
                size_t base = (size_t)(TILE * jj + tid) * NSLOT;
                g_partial[base + 2 * ii] = v;
                g_partial[base + 2 * ii + 1] = 0.f;
            }
        }
    }
}

// ---------------- Kernel 3: per-row logsumexp + fused final reduce --------------
__global__ void finalize_kernel(float* __restrict__ out) {
    const int tid = threadIdx.x, lane = tid & 31;
    const int row = blockIdx.x * 32 + (tid >> 3);
    const float4* p = (const float4*)&g_partial[(size_t)row * NSLOT + (tid & 7) * 16];
    float4 a = p[0], b = p[1], c = p[2], d = p[3];
    float s = (a.x + a.y + a.z + a.w) + (b.x + b.y + b.z + b.w)
            + (c.x + c.y + c.z + c.w) + (d.x + d.y + d.z + d.w);
    s += __shfl_xor_sync(0xffffffffu, s, 1);
    s += __shfl_xor_sync(0xffffffffu, s, 2);
    s += __shfl_xor_sync(0xffffffffu, s, 4);
    float val = ((tid & 7) == 0) ? (logf(s) - g_slabel[row]) : 0.f;
    val += __shfl_xor_sync(0xffffffffu, val, 8);
    val += __shfl_xor_sync(0xffffffffu, val, 16);
    __shared__ float ws[8];
    __shared__ unsigned islast;
    if (lane == 0) ws[tid >> 5] = val;
    __syncthreads();
    if (tid == 0) {
        float t = 0.f;
        #pragma unroll
        for (int i = 0; i < 8; i++) t += ws[i];
        g_bsum[blockIdx.x] = t;
        __threadfence();
        unsigned tk = atomicAdd(&g_ticket, 1u);
        islast = (tk == gridDim.x - 1) ? 1u : 0u;
    }
    __syncthreads();
    if (islast && tid < 32) {
        float v = 0.f;
        #pragma unroll
        for (int i = 0; i < 8; i++) v += g_bsum[tid * 8 + i];
        #pragma unroll
        for (int o = 16; o > 0; o >>= 1) v += __shfl_xor_sync(0xffffffffu, v, o);
        if (tid == 0) {
            out[0] = v / (float)NROWS;
            g_ticket = 0;
        }
    }
}

extern "C" void kernel_launch(void* const* d_in, const int* in_sizes, int n_in,
                              void* d_out, int out_size) {
    const float* zi = (const float*)d_in[0];
    const float* zj = (const float*)d_in[1];
    float* out = (float*)d_out;

    cudaFuncSetAttribute(simloss_kernel,
                         cudaFuncAttributeMaxDynamicSharedMemorySize, 98304);

    normalize_kernel<<<NROWS / 8, 256>>>(zi, zj);
    simloss_kernel<<<GEMM_CTAS, 256, 98304>>>();
    finalize_kernel<<<256, 256>>>(out);
}

// round 11
// speedup vs baseline: 1.4372x; 1.4372x over previous
#include <cuda_runtime.h>
#include <cuda_bf16.h>
#include <cuda_fp8.h>
#include <cstdint>
#include <math.h>

// NT-Xent loss, symmetric-triangle fp8 mma.sync, intra-warp MMA/epilogue overlap.

#define NROWS 8192
#define HALF_N 4096
#define DIM 256
#define TILE 128
#define GEMM_CTAS 296       // 148 SMs x occ 2, single wave
#define ROWB 256            // bytes per tile row (256 fp8)
#define NSLOT 128
#define SCALE_EX2 2.8853900817779268f   // 2/ln2 : exp(2x) = 2^(x*SCALE)

__device__ __align__(16) uint8_t g_zq[NROWS * DIM];
__device__ float g_partial[(size_t)NROWS * NSLOT];
__device__ float g_slabel[NROWS];
__device__ float g_bsum[256];
__device__ unsigned g_ticket = 0;

__device__ __forceinline__ uint32_t smem_u32(const void* p) {
    uint32_t a;
    asm("{ .reg .u64 t; cvta.to.shared.u64 t, %1; cvt.u32.u64 %0, t; }" : "=r"(a) : "l"(p));
    return a;
}
__device__ __forceinline__ float ex2f(float x) {
    float r;
    asm("ex2.approx.f32 %0, %1;" : "=f"(r) : "f"(x));
    return r;
}

#define CP16(dst, src) asm volatile("cp.async.cg.shared.global [%0], [%1], 16;" :: "r"(dst), "l"(src) : "memory")
#define CP_COMMIT()    asm volatile("cp.async.commit_group;" ::: "memory")
#define CP_WAIT1()     asm volatile("cp.async.wait_group 1;" ::: "memory")
#define CP_WAIT0()     asm volatile("cp.async.wait_group 0;" ::: "memory")

__device__ __forceinline__ void ldm_x4(uint32_t* r, uint32_t addr) {
    asm volatile("ldmatrix.sync.aligned.m8n8.x4.shared.b16 {%0,%1,%2,%3}, [%4];"
                 : "=r"(r[0]), "=r"(r[1]), "=r"(r[2]), "=r"(r[3]) : "r"(addr));
}
__device__ __forceinline__ void mma_fp8(float* c, const uint32_t* a, uint32_t b0, uint32_t b1) {
    asm volatile("mma.sync.aligned.m16n8k32.row.col.f32.e4m3.e4m3.f32 "
                 "{%0,%1,%2,%3}, {%4,%5,%6,%7}, {%8,%9}, {%0,%1,%2,%3};"
                 : "+f"(c[0]), "+f"(c[1]), "+f"(c[2]), "+f"(c[3])
                 : "r"(a[0]), "r"(a[1]), "r"(a[2]), "r"(a[3]), "r"(b0), "r"(b1));
}

__device__ __forceinline__ void tile_ij(int t, int& i, int& j) {
    int p = t / 65;
    int q = t - p * 65;
    if (q < 64 - p) { i = p; j = p + q; }
    else            { i = 63 - p; j = q - 1; }
}

__device__ __forceinline__ void load_tile(uint32_t dst, int tile, int tid) {
    const char* base = (const char*)g_zq + (size_t)tile * TILE * ROWB;
    #pragma unroll
    for (int i = 0; i < 8; i++) {
        int idx = tid + 256 * i;
        int r = idx >> 4;
        int c = idx & 15;
        uint32_t d = dst + r * ROWB + ((c ^ (r & 7)) << 4);
        CP16(d, base + (size_t)r * ROWB + c * 16);
    }
}

// ---------------- Kernel 1: normalize fp32 -> e4m3, warp per row ----------------
__global__ void normalize_kernel(const float* __restrict__ zi,
                                 const float* __restrict__ zj) {
    const int wid = threadIdx.x >> 5, lane = threadIdx.x & 31;
    const int row = blockIdx.x * 8 + wid;
    const float* src = (row < HALF_N) ? (zi + (size_t)row * DIM)
                                      : (zj + (size_t)(row - HALF_N) * DIM);
    const float4* s4 = (const float4*)src;
    float4 a = s4[lane * 2];
    float4 b = s4[lane * 2 + 1];
    float ss = a.x*a.x + a.y*a.y + a.z*a.z + a.w*a.w
             + b.x*b.x + b.y*b.y + b.z*b.z + b.w*b.w;
    #pragma unroll
    for (int o = 16; o > 0; o >>= 1) ss += __shfl_xor_sync(0xffffffffu, ss, o);
    float inv = rsqrtf(fmaxf(ss, 1e-16f));
    unsigned short q0 = __nv_cvt_float2_to_fp8x2(make_float2(a.x*inv, a.y*inv), __NV_SATFINITE, __NV_E4M3);
    unsigned short q1 = __nv_cvt_float2_to_fp8x2(make_float2(a.z*inv, a.w*inv), __NV_SATFINITE, __NV_E4M3);
    unsigned short q2 = __nv_cvt_float2_to_fp8x2(make_float2(b.x*inv, b.y*inv), __NV_SATFINITE, __NV_E4M3);
    unsigned short q3 = __nv_cvt_float2_to_fp8x2(make_float2(b.z*inv, b.w*inv), __NV_SATFINITE, __NV_E4M3);
    uint2 out;
    out.x = (uint32_t)q0 | ((uint32_t)q1 << 16);
    out.y = (uint32_t)q2 | ((uint32_t)q3 << 16);
    *(uint2*)(g_zq + (size_t)row * ROWB + lane * 8) = out;
}

// ---------------- Kernel 2: triangle sim GEMM + overlapped exp-sum --------------
__global__ __launch_bounds__(256, 2) void simloss_kernel() {
    extern __shared__ char smem[];
    __shared__ float colstage[4][128];
    const uint32_t sb = smem_u32(smem);
    const uint32_t A_OFF = sb;
    const uint32_t B_OFF[2] = { sb + 32768, sb + 65536 };

    const int tid = threadIdx.x, wid = tid >> 5, lane = tid & 31;
    const int wm = wid & 3, wn = wid >> 2;
    const int b = blockIdx.x;
    const int t0 = b * 7 + min(b, 8);
    const int cnt = 7 + (b < 8 ? 1 : 0);

    int i0, j0, i1x, j1x;
    tile_ij(t0, i0, j0);
    tile_ij(t0 + 1, i1x, j1x);
    load_tile(A_OFF, i0, tid);
    load_tile(B_OFF[0], j0, tid);
    CP_COMMIT();
    load_tile(B_OFF[1], j1x, tid);
    CP_COMMIT();

    const int h = lane >> 4;
    uint32_t a_row[2], a_x[2];
    #pragma unroll
    for (int m = 0; m < 2; m++) {
        int r = wm * 32 + m * 16 + (lane & 15);
        a_row[m] = A_OFF + r * ROWB;
        a_x[m] = r & 7;
    }
    uint32_t b_row[4], b_x[4];
    #pragma unroll
    for (int n = 0; n < 4; n++) {
        int r = wn * 64 + n * 16 + (lane & 15);
        b_row[n] = r * ROWB;
        b_x[n] = r & 7;
    }

    const int lr = lane >> 2;
    const int c4 = lane & 3;

    int iprev = i0;
    for (int k = 0; k < cnt; k++) {
        int ii, jj;
        tile_ij(t0 + k, ii, jj);
        const bool achg = (k > 0) && (ii != iprev);
        iprev = ii;

        if (achg) CP_WAIT0(); else CP_WAIT1();
        __syncthreads();

        const uint32_t bb = B_OFF[k & 1];
        float acc[2][8][4];
        #pragma unroll
        for (int m = 0; m < 2; m++)
            #pragma unroll
            for (int n = 0; n < 8; n++)
                #pragma unroll
                for (int q = 0; q < 4; q++) acc[m][n][q] = 0.f;

        // ---- Phase 1: MMA half-0 (B groups 0,1 -> acc[m][0..3]) ----
        #pragma unroll
        for (int ks = 0; ks < 8; ks++) {
            const uint32_t c = 2 * ks + h;
            uint32_t ar[2][4], br[2][4];
            #pragma unroll
            for (int m = 0; m < 2; m++)
                ldm_x4(ar[m], a_row[m] + ((c ^ a_x[m]) << 4));
            #pragma unroll
            for (int n = 0; n < 2; n++)
                ldm_x4(br[n], bb + b_row[n] + ((c ^ b_x[n]) << 4));
            #pragma unroll
            for (int m = 0; m < 2; m++)
                #pragma unroll
                for (int n = 0; n < 2; n++) {
                    mma_fp8(acc[m][2 * n],     ar[m], br[n][0], br[n][2]);
                    mma_fp8(acc[m][2 * n + 1], ar[m], br[n][1], br[n][3]);
                }
        }

        const bool isdiag = (ii == jj);
        const bool islab = ((ii ^ jj) == 32);
        const bool special = isdiag || islab;       // uniform per CTA

        float rs[2][2] = {{0.f, 0.f}, {0.f, 0.f}};
        float cs[8][2];
        #pragma unroll
        for (int n = 0; n < 8; n++) { cs[n][0] = 0.f; cs[n][1] = 0.f; }

        // ---- Phase 2: MMA half-1 interleaved with epilogue chunks of half-0 ----
        if (!special) {
            #pragma unroll
            for (int ks = 0; ks < 8; ks++) {
                const uint32_t c = 2 * ks + h;
                uint32_t ar[2][4], br[2][4];
                #pragma unroll
                for (int m = 0; m < 2; m++)
                    ldm_x4(ar[m], a_row[m] + ((c ^ a_x[m]) << 4));
                #pragma unroll
                for (int n = 0; n < 2; n++)
                    ldm_x4(br[n], bb + b_row[n + 2] + ((c ^ b_x[n + 2]) << 4));
                #pragma unroll
                for (int m = 0; m < 2; m++)
                    #pragma unroll
                    for (int n = 0; n < 2; n++) {
                        mma_fp8(acc[m][4 + 2 * n],     ar[m], br[n][0], br[n][2]);
                        mma_fp8(acc[m][4 + 2 * n + 1], ar[m], br[n][1], br[n][3]);
                    }
                // Epilogue chunk: 4 elements of half-0 (independent of above MMAs)
                const int mc = ks & 1, nc = ks >> 1;
                #pragma unroll
                for (int q = 0; q < 4; q++) {
                    float e = ex2f(acc[mc][nc][q] * SCALE_EX2);
                    rs[mc][q >> 1] += e;
                    cs[nc][q & 1] += e;
                }
            }
        } else {
            #pragma unroll
            for (int ks = 0; ks < 8; ks++) {
                const uint32_t c = 2 * ks + h;
                uint32_t ar[2][4], br[2][4];
                #pragma unroll
                for (int m = 0; m < 2; m++)
                    ldm_x4(ar[m], a_row[m] + ((c ^ a_x[m]) << 4));
                #pragma unroll
                for (int n = 0; n < 2; n++)
                    ldm_x4(br[n], bb + b_row[n + 2] + ((c ^ b_x[n + 2]) << 4));
                #pragma unroll
                for (int m = 0; m < 2; m++)
                    #pragma unroll
                    for (int n = 0; n < 2; n++) {
                        mma_fp8(acc[m][4 + 2 * n],     ar[m], br[n][0], br[n][2]);
                        mma_fp8(acc[m][4 + 2 * n + 1], ar[m], br[n][1], br[n][3]);
                    }
            }
        }

        __syncthreads();            // done reading smem tiles

        if (k + 1 < cnt) {
            int in, jn;
            tile_ij(t0 + k + 1, in, jn);
            if (in != ii) load_tile(A_OFF, in, tid);
        }
        if (k + 2 < cnt) {
            int in2, jn2;
            tile_ij(t0 + k + 2, in2, jn2);
            load_tile(B_OFF[k & 1], jn2, tid);
        }
        CP_COMMIT();

        if (!special) {
            // ---- Phase 3: epilogue half-1 (overlaps cp.async) ----
            #pragma unroll
            for (int m = 0; m < 2; m++)
                #pragma unroll
                for (int n = 4; n < 8; n++)
                    #pragma unroll
                    for (int q = 0; q < 4; q++) {
                        float e = ex2f(acc[m][n][q] * SCALE_EX2);
                        rs[m][q >> 1] += e;
                        cs[n][q & 1] += e;
                    }
        } else {
            // Exact path for diag/label tiles (96 of 2080).
            #pragma unroll
            for (int m = 0; m < 2; m++)
                #pragma unroll
                for (int n = 0; n < 8; n++)
                    #pragma unroll
                    for (int q = 0; q < 4; q++) {
                        const int rh = q >> 1, kp = q & 1;
                        const int rloc = wm * 32 + m * 16 + lr + rh * 8;
                        const int cloc = wn * 64 + n * 8 + c4 * 2 + kp;
                        float e = ex2f(acc[m][n][q] * SCALE_EX2);
                        bool dg = isdiag && (rloc == cloc);
                        if (!dg) { rs[m][rh] += e; cs[n][kp] += e; }
                        if (islab && rloc == cloc) {
                            float s = 2.0f * acc[m][n][q];
                            g_slabel[TILE * ii + rloc] = s;
                            g_slabel[TILE * jj + cloc] = s;
                        }
                    }
        }

        // Row reduce (lane bits 0-1).
        #pragma unroll
        for (int m = 0; m < 2; m++)
            #pragma unroll
            for (int rh = 0; rh < 2; rh++) {
                rs[m][rh] += __shfl_xor_sync(0xffffffffu, rs[m][rh], 1);
                rs[m][rh] += __shfl_xor_sync(0xffffffffu, rs[m][rh], 2);
            }
        if (c4 == 0) {
            #pragma unroll
            for (int m = 0; m < 2; m++)
                #pragma unroll
                for (int rh = 0; rh < 2; rh++) {
                    int grow = TILE * ii + wm * 32 + m * 16 + lr + rh * 8;
                    g_partial[(size_t)grow * NSLOT + 2 * jj + wn] = rs[m][rh];
                }
        }

        // Column reduce (lane bits 2-4 in-warp, wm via smem).
        #pragma unroll
        for (int n = 0; n < 8; n++)
            #pragma unroll
            for (int kp = 0; kp < 2; kp++) {
                cs[n][kp] += __shfl_xor_sync(0xffffffffu, cs[n][kp], 4);
                cs[n][kp] += __shfl_xor_sync(0xffffffffu, cs[n][kp], 8);
                cs[n][kp] += __shfl_xor_sync(0xffffffffu, cs[n][kp], 16);
            }
        if (lane < 4) {
            #pragma unroll
            for (int n = 0; n < 8; n++)
                #pragma unroll
                for (int kp = 0; kp < 2; kp++)
                    colstage[wm][wn * 64 + n * 8 + lane * 2 + kp] = cs[n][kp];
        }
        __syncthreads();
        if (!isdiag && tid < 128) {
            float v = colstage[0][tid] + colstage[1][tid]
                    + colstage[2][tid] + colstage[3][tid];
            size_t base = (size_t)(TILE * jj + tid) * NSLOT;
            g_partial[base + 2 * ii] = v;
            g_partial[base + 2 * ii + 1] = 0.f;
        }
    }
}

// ---------------- Kernel 3: per-row logsumexp + fused final reduce --------------
__global__ void finalize_kernel(float* __restrict__ out) {
    const int tid = threadIdx.x, lane = tid & 31;
    const int row = blockIdx.x * 32 + (tid >> 3);
    const float4* p = (const float4*)&g_partial[(size_t)row * NSLOT + (tid & 7) * 16];
    float4 a = p[0], b = p[1], c = p[2], d = p[3];
    float s = (a.x + a.y + a.z + a.w) + (b.x + b.y + b.z + b.w)
            + (c.x + c.y + c.z + c.w) + (d.x + d.y + d.z + d.w);
    s += __shfl_xor_sync(0xffffffffu, s, 1);
    s += __shfl_xor_sync(0xffffffffu, s, 2);
    s += __shfl_xor_sync(0xffffffffu, s, 4);
    float val = ((tid & 7) == 0) ? (logf(s) - g_slabel[row]) : 0.f;
    val += __shfl_xor_sync(0xffffffffu, val, 8);
    val += __shfl_xor_sync(0xffffffffu, val, 16);
    __shared__ float ws[8];
    __shared__ unsigned islast;
    if (lane == 0) ws[tid >> 5] = val;
    __syncthreads();
    if (tid == 0) {
        float t = 0.f;
        #pragma unroll
        for (int i = 0; i < 8; i++) t += ws[i];
        g_bsum[blockIdx.x] = t;
        __threadfence();
        unsigned tk = atomicAdd(&g_ticket, 1u);
        islast = (tk == gridDim.x - 1) ? 1u : 0u;
    }
    __syncthreads();
    if (islast && tid < 32) {
        float v = 0.f;
        #pragma unroll
        for (int i = 0; i < 8; i++) v += g_bsum[tid * 8 + i];
        #pragma unroll
        for (int o = 16; o > 0; o >>= 1) v += __shfl_xor_sync(0xffffffffu, v, o);
        if (tid == 0) {
            out[0] = v / (float)NROWS;
            g_ticket = 0;
        }
    }
}

extern "C" void kernel_launch(void* const* d_in, const int* in_sizes, int n_in,
                              void* d_out, int out_size) {
    const float* zi = (const float*)d_in[0];
    const float* zj = (const float*)d_in[1];
    float* out = (float*)d_out;

    cudaFuncSetAttribute(simloss_kernel,
                         cudaFuncAttributeMaxDynamicSharedMemorySize, 98304);

    normalize_kernel<<<NROWS / 8, 256>>>(zi, zj);
    simloss_kernel<<<GEMM_CTAS, 256, 98304>>>();
    finalize_kernel<<<256, 256>>>(out);
}